// round 1
// baseline (speedup 1.0000x reference)
#include <cuda_runtime.h>

// DentateGyrus: out = binary spike vector from Izhikevich step driven by
// injected_current = 10 * (W @ ec).
// Inputs (metadata order):
//   0: ec_spike_vector            float32 [8192]
//   1: W                          float32 [32768, 8192]
//   2: membrane_potential         float32 [32768]
//   3: recovery_variable          float32 [32768]
//   4: recovery_time_constant     (unused for output)
//   5: subthreshold_coupling      (unused)
//   6: spike_reset_voltage        (unused)
//   7: after_hyperpolarization_jump (unused)
// Output: float32 [32768]
//
// Note: the reference's top-K sparsification over a {0,1} vector is an
// identity (threshold is 0 or 1; (s>=thr)*s == s in both cases), so the
// output is exactly the binary spike vector.

#ifndef ENTRY_DIM
#define ENTRY_DIM 8192
#endif
#define NROWS 32768
#define DTSTEP 0.5f
#define WARPS_PER_BLOCK 8
#define TPB (WARPS_PER_BLOCK * 32)

__global__ __launch_bounds__(TPB, 1)
void dg_gemv_spike(const float* __restrict__ ec,
                   const float* __restrict__ W,
                   const float* __restrict__ v_in,
                   const float* __restrict__ u_in,
                   float* __restrict__ out)
{
    // Stage ec (8192 f32 = 32 KB) in shared memory, vectorized.
    __shared__ float4 ecs[ENTRY_DIM / 4];
    const float4* ec4 = reinterpret_cast<const float4*>(ec);
    for (int i = threadIdx.x; i < ENTRY_DIM / 4; i += TPB) {
        ecs[i] = ec4[i];
    }
    __syncthreads();

    const int warp = threadIdx.x >> 5;
    const int lane = threadIdx.x & 31;
    const int row  = blockIdx.x * WARPS_PER_BLOCK + warp;
    if (row >= NROWS) return;

    const float4* __restrict__ Wr =
        reinterpret_cast<const float4*>(W + (size_t)row * ENTRY_DIM);

    // 8192 floats / 4 / 32 lanes = 64 float4 per lane, fully coalesced:
    // each iteration the warp touches one contiguous 512B span.
    float a0 = 0.f, a1 = 0.f, a2 = 0.f, a3 = 0.f;
    #pragma unroll 8
    for (int it = 0; it < ENTRY_DIM / 4 / 32; ++it) {
        float4 w = Wr[it * 32 + lane];
        float4 e = ecs[it * 32 + lane];
        a0 = fmaf(w.x, e.x, a0);
        a1 = fmaf(w.y, e.y, a1);
        a2 = fmaf(w.z, e.z, a2);
        a3 = fmaf(w.w, e.w, a3);
    }
    float acc = (a0 + a1) + (a2 + a3);

    // Warp reduction.
    #pragma unroll
    for (int off = 16; off > 0; off >>= 1)
        acc += __shfl_xor_sync(0xffffffffu, acc, off);

    if (lane == 0) {
        const float I  = acc * 10.0f;
        const float v  = v_in[row];
        const float u  = u_in[row];
        const float dv = 0.04f * v * v + 5.0f * v + 140.0f - u + I;
        const float vn = fmaf(dv, DTSTEP, v);
        out[row] = (vn >= 30.0f) ? 1.0f : 0.0f;
    }
}

extern "C" void kernel_launch(void* const* d_in, const int* in_sizes, int n_in,
                              void* d_out, int out_size)
{
    const float* ec = (const float*)d_in[0];
    const float* W  = (const float*)d_in[1];
    const float* v  = (const float*)d_in[2];
    const float* u  = (const float*)d_in[3];
    float* out = (float*)d_out;

    (void)in_sizes; (void)n_in; (void)out_size;

    const int blocks = NROWS / WARPS_PER_BLOCK; // 4096
    dg_gemv_spike<<<blocks, TPB>>>(ec, W, v, u, out);
}

// round 2
// speedup vs baseline: 1.1198x; 1.1198x over previous
#include <cuda_runtime.h>

// DentateGyrus: out = binary spike vector from Izhikevich step driven by
// injected_current = 10 * (W @ ec). Top-K over a {0,1} vector is an identity,
// so output == binary spike vector.
//
// R2: persistent single-wave kernel (grid = 148 SMs x 4 blocks), register-capped
// to 4 blocks/SM, unroll-4 row streaming. ec staged in smem once per block.

#ifndef ENTRY_DIM
#define ENTRY_DIM 8192
#endif
#define NROWS 32768
#define DTSTEP 0.5f
#define WARPS_PER_BLOCK 8
#define TPB (WARPS_PER_BLOCK * 32)
#define NUM_SMS 148
#define BLOCKS_PER_SM 4
#define GRID (NUM_SMS * BLOCKS_PER_SM)   // 592 blocks, one wave

__global__ __launch_bounds__(TPB, BLOCKS_PER_SM)
void dg_gemv_spike(const float* __restrict__ ec,
                   const float* __restrict__ W,
                   const float* __restrict__ v_in,
                   const float* __restrict__ u_in,
                   float* __restrict__ out)
{
    // Stage ec (8192 f32 = 32 KB) in shared memory once per (persistent) block.
    __shared__ float4 ecs[ENTRY_DIM / 4];
    const float4* ec4 = reinterpret_cast<const float4*>(ec);
    #pragma unroll
    for (int i = threadIdx.x; i < ENTRY_DIM / 4; i += TPB) {
        ecs[i] = ec4[i];
    }
    __syncthreads();

    const int warp  = threadIdx.x >> 5;
    const int lane  = threadIdx.x & 31;
    const int gwarp = blockIdx.x * WARPS_PER_BLOCK + warp;   // 0..4735
    const int nwarp = GRID * WARPS_PER_BLOCK;                 // 4736

    for (int row = gwarp; row < NROWS; row += nwarp) {
        const float4* __restrict__ Wr =
            reinterpret_cast<const float4*>(W + (size_t)row * ENTRY_DIM);

        // 64 float4 per lane, coalesced 512B warp spans, 4 loads in flight.
        float a0 = 0.f, a1 = 0.f, a2 = 0.f, a3 = 0.f;
        #pragma unroll 4
        for (int it = 0; it < ENTRY_DIM / 4 / 32; ++it) {
            float4 w = Wr[it * 32 + lane];
            float4 e = ecs[it * 32 + lane];
            a0 = fmaf(w.x, e.x, a0);
            a1 = fmaf(w.y, e.y, a1);
            a2 = fmaf(w.z, e.z, a2);
            a3 = fmaf(w.w, e.w, a3);
        }
        float acc = (a0 + a1) + (a2 + a3);

        #pragma unroll
        for (int off = 16; off > 0; off >>= 1)
            acc += __shfl_xor_sync(0xffffffffu, acc, off);

        if (lane == 0) {
            const float I  = acc * 10.0f;
            const float v  = v_in[row];
            const float u  = u_in[row];
            const float dv = 0.04f * v * v + 5.0f * v + 140.0f - u + I;
            const float vn = fmaf(dv, DTSTEP, v);
            out[row] = (vn >= 30.0f) ? 1.0f : 0.0f;
        }
    }
}

extern "C" void kernel_launch(void* const* d_in, const int* in_sizes, int n_in,
                              void* d_out, int out_size)
{
    const float* ec = (const float*)d_in[0];
    const float* W  = (const float*)d_in[1];
    const float* v  = (const float*)d_in[2];
    const float* u  = (const float*)d_in[3];
    float* out = (float*)d_out;

    (void)in_sizes; (void)n_in; (void)out_size;

    dg_gemv_spike<<<GRID, TPB>>>(ec, W, v, u, out);
}